// round 1
// baseline (speedup 1.0000x reference)
#include <cuda_runtime.h>
#include <math.h>

#define Bv 4
#define Nv 4096
#define Kv 32
#define Cv 192
#define CH (Cv + 3)      // 195 input channels (3 dp + 192 agg)
#define FD 32            // feat_dim = C/6
#define HSTRIDE 36       // padded row stride (16B aligned, reduces STS conflicts)

// Scratch (no allocation allowed)
__device__ float g_xt[Bv * Nv * Cv];   // (x + 1) transposed to [b][n][c]
__device__ float g_wt[CH * Cv];        // BN-folded weight, [c][o]
__device__ float g_bias[Cv];           // beta - rmean*inv
__device__ float g_invm[FD];           // 500^(-f/32), double-accurate

// ---------------------------------------------------------------------------
// Kernel 1: transpose x [B,C,N] -> xt [B,N,C], fused +1 (agg = pe*(x+1))
// ---------------------------------------------------------------------------
__global__ void transpose_add1(const float* __restrict__ x) {
    __shared__ float tile[32][33];
    int n0 = blockIdx.x * 32, c0 = blockIdx.y * 32, b = blockIdx.z;
    int tx = threadIdx.x, ty = threadIdx.y;
#pragma unroll
    for (int i = 0; i < 4; i++) {
        int c = c0 + ty + i * 8;
        tile[ty + i * 8][tx] = x[((size_t)b * Cv + c) * Nv + n0 + tx];
    }
    __syncthreads();
#pragma unroll
    for (int i = 0; i < 4; i++) {
        int n = n0 + ty + i * 8;
        g_xt[((size_t)b * Nv + n) * Cv + c0 + tx] = tile[tx][ty + i * 8] + 1.0f;
    }
}

// ---------------------------------------------------------------------------
// Kernel 2: fold BN into W, transpose to [c][o]; bias; inv dim_mat table
// ---------------------------------------------------------------------------
__global__ void prep_w(const float* __restrict__ W, const float* __restrict__ gamma,
                       const float* __restrict__ beta, const float* __restrict__ rmean,
                       const float* __restrict__ rvar) {
    int t = blockIdx.x * blockDim.x + threadIdx.x;
    if (t < CH * Cv) {
        int o = t % Cv, c = t / Cv;
        float inv = gamma[o] * rsqrtf(rvar[o] + 1e-5f);
        g_wt[c * Cv + o] = W[o * CH + c] * inv;
    }
    if (t < Cv) {
        float inv = gamma[t] * rsqrtf(rvar[t] + 1e-5f);
        g_bias[t] = beta[t] - rmean[t] * inv;
    }
    if (t < FD) {
        // log2(500) = 8.965784284662087...
        g_invm[t] = (float)exp2(-(double)t * (8.9657842846620870436 / 32.0));
    }
}

// ---------------------------------------------------------------------------
// Kernel 3: main fused kernel. One CTA per (b, n). 192 threads.
//   Phase 1: dp (3 x 32) from p gather
//   Phase 2: sin/cos positional embedding * (x+1) -> H[195][HSTRIDE] in smem
//   Phase 3: y[o][k] = sum_c Wt[c][o] * H[c][k] via packed f32x2 FMA,
//            then max over k, +bias, ReLU
// ---------------------------------------------------------------------------
__global__ void __launch_bounds__(192) local_agg_main(
    const float* __restrict__ p, const int* __restrict__ idx,
    float* __restrict__ out)
{
    __shared__ float Hs[CH * HSTRIDE];
    __shared__ float sa[3 * Kv];   // 50*dp
    __shared__ int   sj[Kv];
    __shared__ float sinvm[FD];

    const int bn = blockIdx.x;
    const int b = bn >> 12;          // N = 4096
    const int n = bn & (Nv - 1);
    const int tid = threadIdx.x;

    // ---- Phase 1: neighbor ids + relative coords ----
    if (tid < Kv) {
        int k = tid;
        int j = idx[(size_t)bn * Kv + k];
        sj[k] = j;
        float cx = p[(size_t)bn * 3 + 0];
        float cy = p[(size_t)bn * 3 + 1];
        float cz = p[(size_t)bn * 3 + 2];
        const float* pj = p + (size_t)(b * Nv + j) * 3;
        float dx = pj[0] - cx, dy = pj[1] - cy, dz = pj[2] - cz;
        Hs[0 * HSTRIDE + k] = dx;
        Hs[1 * HSTRIDE + k] = dy;
        Hs[2 * HSTRIDE + k] = dz;
        sa[0 * Kv + k] = 50.0f * dx;
        sa[1 * Kv + k] = 50.0f * dy;
        sa[2 * Kv + k] = 50.0f * dz;
    } else if (tid < Kv + FD) {
        sinvm[tid - Kv] = g_invm[tid - Kv];
    }
    __syncthreads();

    // ---- Phase 2: positional embedding fused with gathered features ----
    // pair id = k*96 + d*32 + f ; warp lanes sweep f (coalesced xt reads)
    constexpr double TWO_PI_D = 6.2831853071795864769252867665590;
    constexpr float  P2_HI  = 6.28125f;  // exact in fp32
    constexpr float  P2_MID = (float)(TWO_PI_D - (double)P2_HI);
    constexpr float  P2_LO  = (float)(TWO_PI_D - (double)P2_HI - (double)P2_MID);
    const float INV_2PI = 0.15915494309189535f;

#pragma unroll 4
    for (int it = 0; it < 16; it++) {
        int pair = it * 192 + tid;
        int f = pair & 31;
        int q = pair >> 5;           // 0..95
        int d = q % 3;
        int k = q / 3;
        float a   = sa[d * Kv + k];
        float arg = a * sinvm[f];
        // Cody-Waite range reduction to [-pi, pi]
        float nr = rintf(arg * INV_2PI);
        float r  = fmaf(nr, -P2_HI, arg);
        r = fmaf(nr, -P2_MID, r);
        r = fmaf(nr, -P2_LO, r);
        float s  = __sinf(r);
        float co = __cosf(r);
        int j = sj[k];
        const float* xr = g_xt + (size_t)(b * Nv + j) * Cv + d * 64 + f;
        float g1 = __ldg(xr);        // (x+1) at channel d*64+f
        float g2 = __ldg(xr + FD);   // (x+1) at channel d*64+32+f
        Hs[(3 + d * 64 + f) * HSTRIDE + k]      = s  * g1;
        Hs[(3 + d * 64 + FD + f) * HSTRIDE + k] = co * g2;
    }
    __syncthreads();

    // ---- Phase 3: GEMM with packed f32x2 FMA. thread = output channel o ----
    unsigned hb = (unsigned)__cvta_generic_to_shared(Hs);
    const float* wp = g_wt + tid;    // Wt[c][o], coalesced over lanes

    unsigned long long acc[16];      // 16 pairs of k-accumulators (fp32x2)
#pragma unroll
    for (int i = 0; i < 16; i++) acc[i] = 0ull;

#pragma unroll 3
    for (int c = 0; c < CH; c++) {
        float w = __ldg(wp + c * Cv);
        unsigned long long w2;
        asm("mov.b64 %0, {%1, %1};" : "=l"(w2) : "f"(w));
        unsigned ra = hb + (unsigned)(c * (HSTRIDE * 4));
#pragma unroll
        for (int qq = 0; qq < 8; qq++) {
            unsigned long long h0, h1;
            asm("ld.shared.v2.u64 {%0, %1}, [%2];"
                : "=l"(h0), "=l"(h1) : "r"(ra + qq * 16u));
            asm("fma.rn.f32x2 %0, %1, %2, %0;" : "+l"(acc[2 * qq])     : "l"(w2), "l"(h0));
            asm("fma.rn.f32x2 %0, %1, %2, %0;" : "+l"(acc[2 * qq + 1]) : "l"(w2), "l"(h1));
        }
    }

    // ---- Epilogue: max over k, add bias, ReLU ----
    float m = -3.402823466e38f;
#pragma unroll
    for (int i = 0; i < 16; i++) {
        float lo, hi;
        asm("mov.b64 {%0, %1}, %2;" : "=f"(lo), "=f"(hi) : "l"(acc[i]));
        m = fmaxf(m, lo);
        m = fmaxf(m, hi);
    }
    float z = m + __ldg(g_bias + tid);
    out[((size_t)b * Cv + tid) * Nv + n] = fmaxf(z, 0.0f);
}

// ---------------------------------------------------------------------------
extern "C" void kernel_launch(void* const* d_in, const int* in_sizes, int n_in,
                              void* d_out, int out_size) {
    const float* p     = (const float*)d_in[0];
    const float* x     = (const float*)d_in[1];
    const int*   idx   = (const int*)d_in[2];
    const float* W     = (const float*)d_in[3];
    const float* gamma = (const float*)d_in[4];
    const float* beta  = (const float*)d_in[5];
    const float* rmean = (const float*)d_in[6];
    const float* rvar  = (const float*)d_in[7];
    float* out = (float*)d_out;

    dim3 tb(32, 8);
    dim3 tg(Nv / 32, Cv / 32, Bv);
    transpose_add1<<<tg, tb>>>(x);
    prep_w<<<(CH * Cv + 255) / 256, 256>>>(W, gamma, beta, rmean, rvar);
    local_agg_main<<<Bv * Nv, 192>>>(p, idx, out);
}